// round 6
// baseline (speedup 1.0000x reference)
#include <cuda_runtime.h>
#include <cstdint>

// Embedding gather: out[token, :] = weight[input[token], :]
// input: [32768] int32, weight: [50257, 512] f32, out: [32768, 512] f32
//
// Steady-state DRAM demand per replay: ~48MB unique weight rows + 67MB
// output writeback ~= 115MB -> at 16.8us that's ~6.85TB/s, i.e. the
// practical LTS/HBM ceiling. Final lever: write-through stores (__stwt)
// push the output stream straight to DRAM instead of parking 67MB of
// dirty lines in L2, freeing LTS tags/capacity for weight-row fills and
// avoiding end-of-replay writeback bursts colliding with the next
// replay's reads. Writes are full 128B sectors, so no RFO either way.
//
// Structure (measured-best): one warp per token row, block's 8 indices
// staged through smem with one coalesced load (kills the dependent
// idx-LDG -> weight-LDG chain), 4 independent float4 loads per thread.

#define WARPS_PER_CTA 8

__global__ __launch_bounds__(WARPS_PER_CTA * 32) void embed_gather_wt(
    const int* __restrict__ idx,
    const float4* __restrict__ weight4,
    float4* __restrict__ out4,
    int n_tokens)
{
    __shared__ int s_rows[WARPS_PER_CTA];

    const int tid  = threadIdx.x;
    const int warp = tid >> 5;
    const int lane = tid & 31;
    const int base = blockIdx.x * WARPS_PER_CTA;

    // One coalesced load fetches all indices for this block.
    if (tid < WARPS_PER_CTA) {
        int t = base + tid;
        s_rows[tid] = (t < n_tokens) ? __ldg(idx + t) : 0;
    }
    __syncthreads();

    const int token = base + warp;
    if (token >= n_tokens) return;
    const int row = s_rows[warp];

    const float4* __restrict__ src = weight4 + (long long)row * 128 + lane;
    float4* __restrict__ dst       = out4    + (long long)token * 128 + lane;

    // 4 independent loads front-batched (MLP=4)
    float4 v0 = __ldg(src);
    float4 v1 = __ldg(src + 32);
    float4 v2 = __ldg(src + 64);
    float4 v3 = __ldg(src + 96);

    // Write-through: don't occupy L2 with the 67MB output stream.
    __stwt(dst,      v0);
    __stwt(dst + 32, v1);
    __stwt(dst + 64, v2);
    __stwt(dst + 96, v3);
}

extern "C" void kernel_launch(void* const* d_in, const int* in_sizes, int n_in,
                              void* d_out, int out_size) {
    const int*   idx    = (const int*)d_in[0];     // [8*4096] int32
    const float* weight = (const float*)d_in[1];   // [50257*512] f32
    float*       out    = (float*)d_out;

    int n_tokens = in_sizes[0];                    // 32768
    int blocks   = (n_tokens + WARPS_PER_CTA - 1) / WARPS_PER_CTA;  // 4096
    embed_gather_wt<<<blocks, WARPS_PER_CTA * 32>>>(
        idx, (const float4*)weight, (float4*)out, n_tokens);
}

// round 7
// speedup vs baseline: 1.1682x; 1.1682x over previous
#include <cuda_runtime.h>
#include <cstdint>

// Embedding gather: out[token, :] = weight[input[token], :]
// input: [32768] int32, weight: [50257, 512] f32, out: [32768, 512] f32
//
// Measured-best structure (R5, 16.83us): one warp per token row, block's
// 8 indices staged via one coalesced load into smem (kills the dependent
// idx-LDG -> weight-LDG chain), 4 independent float4 loads per thread
// (MLP=4), __stcs evict-first streaming stores (write-through regressed:
// L2 write buffering matters for the 67MB output stream).
//
// This round: weight loads use __ldcg (cache-global, L2-only). Each 2KB
// row is consumed by exactly one warp and cross-warp repeats land on other
// SMs, so L1 allocation is pure overhead (fills/tags with ~0% hit rate).
// Skipping L1 shortens the l1tex wavefront queue — the cross-CTA
// contention point — while keeping L2 reuse of repeated rows.

#define WARPS_PER_CTA 8

__global__ __launch_bounds__(WARPS_PER_CTA * 32) void embed_gather_cg(
    const int* __restrict__ idx,
    const float4* __restrict__ weight4,
    float4* __restrict__ out4,
    int n_tokens)
{
    __shared__ int s_rows[WARPS_PER_CTA];

    const int tid  = threadIdx.x;
    const int warp = tid >> 5;
    const int lane = tid & 31;
    const int base = blockIdx.x * WARPS_PER_CTA;

    // One coalesced load fetches all indices for this block.
    if (tid < WARPS_PER_CTA) {
        int t = base + tid;
        s_rows[tid] = (t < n_tokens) ? __ldg(idx + t) : 0;
    }
    __syncthreads();

    const int token = base + warp;
    if (token >= n_tokens) return;
    const int row = s_rows[warp];

    const float4* __restrict__ src = weight4 + (long long)row * 128 + lane;
    float4* __restrict__ dst       = out4    + (long long)token * 128 + lane;

    // 4 independent L2-only loads front-batched (MLP=4, no L1 allocation)
    float4 v0 = __ldcg(src);
    float4 v1 = __ldcg(src + 32);
    float4 v2 = __ldcg(src + 64);
    float4 v3 = __ldcg(src + 96);

    // Evict-first streaming writeback through L2 (measured best).
    __stcs(dst,      v0);
    __stcs(dst + 32, v1);
    __stcs(dst + 64, v2);
    __stcs(dst + 96, v3);
}

extern "C" void kernel_launch(void* const* d_in, const int* in_sizes, int n_in,
                              void* d_out, int out_size) {
    const int*   idx    = (const int*)d_in[0];     // [8*4096] int32
    const float* weight = (const float*)d_in[1];   // [50257*512] f32
    float*       out    = (float*)d_out;

    int n_tokens = in_sizes[0];                    // 32768
    int blocks   = (n_tokens + WARPS_PER_CTA - 1) / WARPS_PER_CTA;  // 4096
    embed_gather_cg<<<blocks, WARPS_PER_CTA * 32>>>(
        idx, (const float4*)weight, (float4*)out, n_tokens);
}

// round 9
// speedup vs baseline: 1.1882x; 1.0171x over previous
#include <cuda_runtime.h>
#include <cstdint>

// Embedding gather: out[token, :] = weight[input[token], :]
// input: [32768] int32, weight: [50257, 512] f32, out: [32768, 512] f32
//
// sm_103a ptxas requires 256-bit (.v8.b32) accesses for L2 eviction hints.
// Weight loads: ld.global.L2::evict_last.v8.b32  -> retain ~48MB unique
//   weight working set in L2 across graph replays.
// Output stores: st.global.L2::evict_first.v8.b32 -> 67MB write stream
//   cannot displace weight lines.
// Bonus: 32B/thread accesses halve LSU instruction count (1024B/warp/instr).
//
// Layout: one warp per token row (2048B = 64 x 32B chunks). Lane t handles
// chunks {t, t+32}: 2 independent front-batched warp loads, 64B in flight
// per thread (matches the measured-best R5 configuration).

#define WARPS_PER_CTA 8

struct __align__(32) f32x8 { uint32_t r[8]; };

__device__ __forceinline__ f32x8 ldg_v8_evict_last(const void* p) {
    f32x8 v;
    asm volatile("ld.global.L2::evict_last.v8.b32 {%0,%1,%2,%3,%4,%5,%6,%7}, [%8];"
                 : "=r"(v.r[0]), "=r"(v.r[1]), "=r"(v.r[2]), "=r"(v.r[3]),
                   "=r"(v.r[4]), "=r"(v.r[5]), "=r"(v.r[6]), "=r"(v.r[7])
                 : "l"(p));
    return v;
}

__device__ __forceinline__ void stg_v8_evict_first(void* p, const f32x8& v) {
    asm volatile("st.global.L2::evict_first.v8.b32 [%0], {%1,%2,%3,%4,%5,%6,%7,%8};"
                 :: "l"(p),
                    "r"(v.r[0]), "r"(v.r[1]), "r"(v.r[2]), "r"(v.r[3]),
                    "r"(v.r[4]), "r"(v.r[5]), "r"(v.r[6]), "r"(v.r[7])
                 : "memory");
}

__global__ __launch_bounds__(WARPS_PER_CTA * 32) void embed_gather_v8(
    const int* __restrict__ idx,
    const char* __restrict__ weight,
    char* __restrict__ out,
    int n_tokens)
{
    __shared__ int s_rows[WARPS_PER_CTA];

    const int tid  = threadIdx.x;
    const int warp = tid >> 5;
    const int lane = tid & 31;
    const int base = blockIdx.x * WARPS_PER_CTA;

    // One coalesced load fetches all indices for this block.
    if (tid < WARPS_PER_CTA) {
        int t = base + tid;
        s_rows[tid] = (t < n_tokens) ? __ldg(idx + t) : 0;
    }
    __syncthreads();

    const int token = base + warp;
    if (token >= n_tokens) return;
    const int row = s_rows[warp];

    const char* __restrict__ src = weight + (long long)row * 2048 + lane * 32;
    char* __restrict__ dst       = out    + (long long)token * 2048 + lane * 32;

    // 2 independent 1024B warp-loads front-batched (64B/thread in flight).
    f32x8 v0 = ldg_v8_evict_last(src);
    f32x8 v1 = ldg_v8_evict_last(src + 1024);

    stg_v8_evict_first(dst,        v0);
    stg_v8_evict_first(dst + 1024, v1);
}

extern "C" void kernel_launch(void* const* d_in, const int* in_sizes, int n_in,
                              void* d_out, int out_size) {
    const int*  idx    = (const int*)d_in[0];     // [8*4096] int32
    const char* weight = (const char*)d_in[1];    // [50257*512] f32 rows
    char*       out    = (char*)d_out;

    int n_tokens = in_sizes[0];                   // 32768
    int blocks   = (n_tokens + WARPS_PER_CTA - 1) / WARPS_PER_CTA;  // 4096
    embed_gather_v8<<<blocks, WARPS_PER_CTA * 32>>>(idx, weight, out, n_tokens);
}